// round 5
// baseline (speedup 1.0000x reference)
#include <cuda_runtime.h>
#include <cuda_bf16.h>

// PointPillarsScatter: out[b, c, y, x] = feat[n, c] where coords[n] = (b, _, y, x), else 0.
// Inverse-index gather: memset g_map to -1; scatter pillar index n into g_map[b,y,x]
// (+ warm L2 with the 12MB feature array so the write pass is a pure DRAM write
// stream); then write the 219MB output exactly once with 256-bit streaming stores.

#define NYd 496
#define NXd 432
#define Cd  64
#define Bd  4
#define HWd (NYd * NXd)          // 214272
#define MAPN (Bd * HWd)          // 857088 ints, 3.4 MB scratch

__device__ int g_map[MAPN];
__device__ int g_sink;           // dead-store sink for the L2-warm sweep

// ---- Kernel 1: scatter pillar index into map + warm L2 with features ----
__global__ void scatter_map_kernel(const int* __restrict__ coords,
                                   const int4* __restrict__ feat4,
                                   int n_total, int n_feat4) {
    int tid = blockIdx.x * blockDim.x + threadIdx.x;
    int nthreads = gridDim.x * blockDim.x;

    if (tid < n_total) {
        int4 cc = ((const int4*)coords)[tid];   // (b, z, y, x)
        g_map[(cc.x * NYd + cc.z) * NXd + cc.w] = tid;
    }

    // L2-warm sweep over features (12.3MB << 126MB L2). Keeps the main write
    // kernel's gathers off DRAM -> fewer read/write turnarounds there.
    int acc = 0;
    for (int i = tid; i < n_feat4; i += nthreads) {
        int4 v = __ldg(&feat4[i]);
        acc |= v.x | v.y | v.z | v.w;
    }
    if (acc == 0x5A5A5A5A) g_sink = acc;   // never-taken in practice; defeats DCE
}

// ---- Kernel 2: gather-write output, 256-bit coalesced streaming stores ----
// One thread per (quarter, b, y, x/8); 16 channels per thread. 'quarter' is the
// outermost dimension so warp lanes stay consecutive in x -> 1KB contiguous
// stores per warp per iteration.
__global__ void __launch_bounds__(256) write_out_kernel(
        const float* __restrict__ feat, float* __restrict__ out) {
    const int XV = NXd / 8;  // 54
    const int CQ = Cd / 4;   // 16 channels per thread
    int tid = blockIdx.x * blockDim.x + threadIdx.x;
    if (tid >= 4 * Bd * NYd * XV) return;

    int t  = tid;
    int x8 = t % XV;  t /= XV;
    int y  = t % NYd; t /= NYd;
    int b  = t % Bd;
    int q  = t / Bd;            // 0..3
    int c0 = q * CQ;            // 0,16,32,48

    const int* mp = &g_map[(b * NYd + y) * NXd + x8 * 8];
    int4 ma = *(const int4*)mp;
    int4 mb = *(const int4*)(mp + 4);

    int m[8] = {ma.x, ma.y, ma.z, ma.w, mb.x, mb.y, mb.z, mb.w};
    int  o[8];
    #pragma unroll
    for (int j = 0; j < 8; j++) o[j] = m[j] * Cd + c0;  // 32-bit offsets, < 2^31

    // out offset for channel c: ((b*C + c0 + c)*NY + y)*NX + x
    float* outp = out + ((b * Cd + c0) * NYd + y) * NXd + x8 * 8;

    #pragma unroll
    for (int c = 0; c < CQ; c++) {
        float v[8];
        #pragma unroll
        for (int j = 0; j < 8; j++)
            v[j] = (m[j] >= 0) ? __ldg(feat + o[j] + c) : 0.0f;

        // 256-bit streaming store (sm_100+): 32B-aligned by construction.
        asm volatile(
            "st.global.cs.v8.b32 [%0], {%1,%2,%3,%4,%5,%6,%7,%8};"
            :: "l"(outp + c * HWd),
               "r"(__float_as_uint(v[0])), "r"(__float_as_uint(v[1])),
               "r"(__float_as_uint(v[2])), "r"(__float_as_uint(v[3])),
               "r"(__float_as_uint(v[4])), "r"(__float_as_uint(v[5])),
               "r"(__float_as_uint(v[6])), "r"(__float_as_uint(v[7]))
            : "memory");
    }
}

extern "C" void kernel_launch(void* const* d_in, const int* in_sizes, int n_in,
                              void* d_out, int out_size) {
    const float* feat   = (const float*)d_in[0];
    const int*   coords = (const int*)d_in[1];
    int n_total = in_sizes[1] / 4;
    int n_feat4 = in_sizes[0] / 4;

    // 1) map := -1 (0xFF bytes) — async memset node, graph-capturable, no alloc
    void* map_ptr = nullptr;
    cudaGetSymbolAddress(&map_ptr, g_map);
    cudaMemsetAsync(map_ptr, 0xFF, (size_t)MAPN * sizeof(int), 0);

    // 2) map[idx] = n, plus L2 warm of feat
    {
        int nthreads = 49152;  // covers n_total=48000; ~16 int4 warm loads/thread
        scatter_map_kernel<<<nthreads / 256, 256>>>(coords, (const int4*)feat,
                                                    n_total, n_feat4);
    }

    // 3) gather-write full output (4 threads per cell-octet: 16 channels each)
    {
        int nthreads = 4 * Bd * NYd * (NXd / 8);   // 428544
        write_out_kernel<<<(nthreads + 255) / 256, 256>>>(feat, (float*)d_out);
    }
}